// round 2
// baseline (speedup 1.0000x reference)
#include <cuda_runtime.h>

// Problem constants
#define Bv 4
#define Tv 4096
#define Cv 1024
#define Hv 16
#define Dh 64
#define Mv (Bv * Tv)          // 16384 rows
#define NSPLIT 16             // ctx T-splits
#define NCHUNK 32             // kcum T-chunks

// ---------------- scratch (device globals; no allocations allowed) --------
__device__ float g_q[Mv * Cv];                       // 64 MB
__device__ float g_k[Mv * Cv];                       // 64 MB
__device__ float g_v[Mv * Cv];                       // 64 MB
__device__ float g_y[Mv * Cv];                       // 64 MB
__device__ float g_ctx[Bv * Hv * Dh * Dh];           // 1 MB   [bh][d][e]
__device__ float g_ctx_part[NSPLIT * Bv * Hv * Dh * Dh]; // 16 MB [split][bh][d][e]
__device__ float g_kcum[Bv * Cv];                    // 16 KB  [b][h*64+d]
__device__ float g_kcum_part[Bv * NCHUNK * Cv];      // 512 KB [b][chunk][c]

// ---------------- SGEMM: C = A[M,K] * B[K,N] + bias, row-major ------------
// 128x128 block tile, BK=16, 256 threads, 8x8 per-thread micro-tile,
// double-buffered shared memory with register prefetch.
#define BM 128
#define BN 128
#define BK 16

__global__ __launch_bounds__(256)
void gemm_bias(const float* __restrict__ A, const float* __restrict__ Bm,
               const float* __restrict__ bias, float* __restrict__ Cm,
               int M, int N, int K)
{
    __shared__ float As[2][BK][BM];   // transposed A tile
    __shared__ float Bs[2][BK][BN];

    const int tid = threadIdx.x;
    const int rowBase = blockIdx.y * BM;
    const int colBase = blockIdx.x * BN;
    const int tx = tid & 15;       // 8 cols each
    const int ty = tid >> 4;       // 8 rows each

    // load-index precompute (2 float4 loads each for A and B per thread)
    int rA[2], cA[2], rB[2], cB[2];
#pragma unroll
    for (int l = 0; l < 2; l++) {
        int idx = tid + l * 256;
        rA[l] = idx >> 2;          // 0..127
        cA[l] = (idx & 3) * 4;     // 0,4,8,12
        rB[l] = idx >> 5;          // 0..15
        cB[l] = (idx & 31) * 4;    // 0..124
    }

    float acc[8][8];
#pragma unroll
    for (int i = 0; i < 8; i++)
#pragma unroll
        for (int j = 0; j < 8; j++) acc[i][j] = 0.f;

    float4 pa[2], pb[2];
    // ---- prologue: fetch tile k0=0 ----
#pragma unroll
    for (int l = 0; l < 2; l++) {
        pa[l] = *(const float4*)&A[(size_t)(rowBase + rA[l]) * K + cA[l]];
        pb[l] = *(const float4*)&Bm[(size_t)rB[l] * N + colBase + cB[l]];
    }
#pragma unroll
    for (int l = 0; l < 2; l++) {
        As[0][cA[l] + 0][rA[l]] = pa[l].x;
        As[0][cA[l] + 1][rA[l]] = pa[l].y;
        As[0][cA[l] + 2][rA[l]] = pa[l].z;
        As[0][cA[l] + 3][rA[l]] = pa[l].w;
        *(float4*)&Bs[0][rB[l]][cB[l]] = pb[l];
    }
    __syncthreads();

    int stage = 0;
    for (int k0 = BK; k0 <= K; k0 += BK) {
        const bool has_next = (k0 < K);
        if (has_next) {
#pragma unroll
            for (int l = 0; l < 2; l++) {
                pa[l] = *(const float4*)&A[(size_t)(rowBase + rA[l]) * K + k0 + cA[l]];
                pb[l] = *(const float4*)&Bm[(size_t)(k0 + rB[l]) * N + colBase + cB[l]];
            }
        }
        // ---- compute current stage ----
#pragma unroll
        for (int kk = 0; kk < BK; kk++) {
            float af[8], bf[8];
            *(float4*)&af[0] = *(const float4*)&As[stage][kk][ty * 8];
            *(float4*)&af[4] = *(const float4*)&As[stage][kk][ty * 8 + 4];
            *(float4*)&bf[0] = *(const float4*)&Bs[stage][kk][tx * 8];
            *(float4*)&bf[4] = *(const float4*)&Bs[stage][kk][tx * 8 + 4];
#pragma unroll
            for (int i = 0; i < 8; i++)
#pragma unroll
                for (int j = 0; j < 8; j++)
                    acc[i][j] += af[i] * bf[j];
        }
        if (has_next) {
            int ns = stage ^ 1;
#pragma unroll
            for (int l = 0; l < 2; l++) {
                As[ns][cA[l] + 0][rA[l]] = pa[l].x;
                As[ns][cA[l] + 1][rA[l]] = pa[l].y;
                As[ns][cA[l] + 2][rA[l]] = pa[l].z;
                As[ns][cA[l] + 3][rA[l]] = pa[l].w;
                *(float4*)&Bs[ns][rB[l]][cB[l]] = pb[l];
            }
            __syncthreads();
            stage = ns;
        }
    }

    // epilogue: + bias, vectorized store
#pragma unroll
    for (int i = 0; i < 8; i++) {
        int r = rowBase + ty * 8 + i;
#pragma unroll
        for (int j = 0; j < 8; j += 4) {
            int c = colBase + tx * 8 + j;
            float4 o;
            o.x = acc[i][j + 0] + bias[c + 0];
            o.y = acc[i][j + 1] + bias[c + 1];
            o.z = acc[i][j + 2] + bias[c + 2];
            o.w = acc[i][j + 3] + bias[c + 3];
            *(float4*)&Cm[(size_t)r * N + c] = o;
        }
    }
}

// ---------------- per-head softmax over last dim (64) ---------------------
// one warp per (row, head): lane handles elements lane and lane+32
__global__ __launch_bounds__(256)
void softmax_head(float* __restrict__ X)
{
    int w    = (blockIdx.x * blockDim.x + threadIdx.x) >> 5;
    int lane = threadIdx.x & 31;
    int row  = w >> 4;
    int h    = w & 15;
    size_t base = (size_t)row * Cv + h * Dh;

    float a = X[base + lane];
    float b = X[base + lane + 32];
    float m = fmaxf(a, b);
#pragma unroll
    for (int o = 16; o > 0; o >>= 1) m = fmaxf(m, __shfl_xor_sync(~0u, m, o));
    a = __expf(a - m);
    b = __expf(b - m);
    float s = a + b;
#pragma unroll
    for (int o = 16; o > 0; o >>= 1) s += __shfl_xor_sync(~0u, s, o);
    float inv = 1.f / s;
    X[base + lane]      = a * inv;
    X[base + lane + 32] = b * inv;
}

// ---------------- kcum partials: sum softmax(k) over 128 t-rows -----------
// grid (Bv, NCHUNK), block 1024: deterministic (no atomics)
__global__ __launch_bounds__(1024)
void kcum_part_kernel()
{
    int b = blockIdx.x;
    int chunk = blockIdx.y;
    int c = threadIdx.x;
    const float* kp = g_k + ((size_t)(b * Tv + chunk * (Tv / NCHUNK))) * Cv + c;
    float s = 0.f;
#pragma unroll 4
    for (int t = 0; t < Tv / NCHUNK; t++) s += kp[(size_t)t * Cv];
    g_kcum_part[((size_t)b * NCHUNK + chunk) * Cv + c] = s;
}

__global__ __launch_bounds__(256)
void kcum_reduce_kernel()
{
    int i = blockIdx.x * blockDim.x + threadIdx.x;   // Bv*Cv threads
    int b = i >> 10, c = i & 1023;
    float s = 0.f;
#pragma unroll
    for (int ch = 0; ch < NCHUNK; ch++)
        s += g_kcum_part[((size_t)b * NCHUNK + ch) * Cv + c];
    g_kcum[i] = s;
}

// ---------------- context partials: sum_t k[t,:]^T v[t,:] per split -------
// grid (Bv*Hv, NSPLIT), block 256; each thread owns a 4x4 sub-block
__global__ __launch_bounds__(256)
void ctx_part_kernel()
{
    int bh = blockIdx.x;
    int b = bh >> 4, h = bh & 15;
    int split = blockIdx.y;
    const int TSPL = Tv / NSPLIT;   // 256

    __shared__ float ks[32][Dh];
    __shared__ float vs[32][Dh];

    int tid = threadIdx.x;
    int td = (tid >> 4) * 4;
    int te = (tid & 15) * 4;
    float acc[4][4];
#pragma unroll
    for (int i = 0; i < 4; i++)
#pragma unroll
        for (int j = 0; j < 4; j++) acc[i][j] = 0.f;

    int t0 = split * TSPL;
    for (int tc = 0; tc < TSPL; tc += 32) {
        for (int i = tid; i < 32 * 16; i += 256) {
            int r  = i >> 4;
            int c4 = (i & 15) * 4;
            size_t g = ((size_t)(b * Tv + t0 + tc + r)) * Cv + h * Dh + c4;
            *(float4*)&ks[r][c4] = *(const float4*)&g_k[g];
            *(float4*)&vs[r][c4] = *(const float4*)&g_v[g];
        }
        __syncthreads();
#pragma unroll 8
        for (int t = 0; t < 32; t++) {
            float kf[4], vf[4];
            *(float4*)kf = *(const float4*)&ks[t][td];
            *(float4*)vf = *(const float4*)&vs[t][te];
#pragma unroll
            for (int i = 0; i < 4; i++)
#pragma unroll
                for (int j = 0; j < 4; j++)
                    acc[i][j] += kf[i] * vf[j];
        }
        __syncthreads();
    }

    float* cp = &g_ctx_part[((size_t)split * (Bv * Hv) + bh) * Dh * Dh];
#pragma unroll
    for (int i = 0; i < 4; i++)
#pragma unroll
        for (int j = 0; j < 4; j++)
            cp[(td + i) * Dh + te + j] = acc[i][j];
}

__global__ __launch_bounds__(256)
void ctx_reduce_kernel()
{
    int i = blockIdx.x * blockDim.x + threadIdx.x;   // Bv*Hv*Dh*Dh threads
    float s = 0.f;
#pragma unroll
    for (int sp = 0; sp < NSPLIT; sp++)
        s += g_ctx_part[(size_t)sp * (Bv * Hv * Dh * Dh) + i];
    g_ctx[i] = s;
}

// ---------------- y = (q @ ctx) * Dinv + q --------------------------------
// grid (Bv*Hv, 16), block 256 (8 warps); warp processes 32 t-rows
__global__ __launch_bounds__(256)
void y_kernel()
{
    int bh = blockIdx.x;
    int b = bh >> 4, h = bh & 15;

    __shared__ float ctxs[Dh][Dh];
    __shared__ float kc[Dh];

    int tid = threadIdx.x;
    for (int i = tid; i < Dh * Dh / 4; i += 256)
        ((float4*)ctxs)[i] = ((const float4*)&g_ctx[(size_t)bh * Dh * Dh])[i];
    if (tid < Dh) kc[tid] = g_kcum[bh * Dh + tid];   // bh*64 == b*1024 + h*64
    __syncthreads();

    int warp = tid >> 5, lane = tid & 31;
    int tbase = blockIdx.y * 256 + warp * 32;

    for (int ti = 0; ti < 32; ti++) {
        int t = tbase + ti;
        size_t base = ((size_t)(b * Tv + t)) * Cv + h * Dh;
        float qlo = g_q[base + lane];
        float qhi = g_q[base + lane + 32];

        float dp = qlo * kc[lane] + qhi * kc[lane + 32];
#pragma unroll
        for (int o = 16; o > 0; o >>= 1) dp += __shfl_xor_sync(~0u, dp, o);
        float dinv = 1.f / dp;

        float ylo = 0.f, yhi = 0.f;
#pragma unroll
        for (int d = 0; d < 32; d++) {
            float qd = __shfl_sync(~0u, qlo, d);
            ylo += qd * ctxs[d][lane];
            yhi += qd * ctxs[d][lane + 32];
        }
#pragma unroll
        for (int d = 0; d < 32; d++) {
            float qd = __shfl_sync(~0u, qhi, d);
            ylo += qd * ctxs[32 + d][lane];
            yhi += qd * ctxs[32 + d][lane + 32];
        }
        g_y[base + lane]      = ylo * dinv + qlo;
        g_y[base + lane + 32] = yhi * dinv + qhi;
    }
}

// ---------------- launch ---------------------------------------------------
extern "C" void kernel_launch(void* const* d_in, const int* in_sizes, int n_in,
                              void* d_out, int out_size)
{
    const float* x  = (const float*)d_in[0];
    const float* Wq = (const float*)d_in[1];
    const float* bq = (const float*)d_in[2];
    const float* Wk = (const float*)d_in[3];
    const float* bk = (const float*)d_in[4];
    const float* Wv = (const float*)d_in[5];
    const float* bv = (const float*)d_in[6];
    const float* Wp = (const float*)d_in[7];
    const float* bp = (const float*)d_in[8];
    float* out = (float*)d_out;

    float *q, *k, *v, *y;
    cudaGetSymbolAddress((void**)&q, g_q);
    cudaGetSymbolAddress((void**)&k, g_k);
    cudaGetSymbolAddress((void**)&v, g_v);
    cudaGetSymbolAddress((void**)&y, g_y);

    dim3 gg(Cv / BN, Mv / BM);   // (8, 128)

    gemm_bias<<<gg, 256>>>(x, Wq, bq, q, Mv, Cv, Cv);
    gemm_bias<<<gg, 256>>>(x, Wk, bk, k, Mv, Cv, Cv);
    gemm_bias<<<gg, 256>>>(x, Wv, bv, v, Mv, Cv, Cv);

    softmax_head<<<(Mv * Hv) / 8, 256>>>(q);
    softmax_head<<<(Mv * Hv) / 8, 256>>>(k);

    kcum_part_kernel<<<dim3(Bv, NCHUNK), 1024>>>();
    kcum_reduce_kernel<<<(Bv * Cv) / 256, 256>>>();
    ctx_part_kernel<<<dim3(Bv * Hv, NSPLIT), 256>>>();
    ctx_reduce_kernel<<<(Bv * Hv * Dh * Dh) / 256, 256>>>();
    y_kernel<<<dim3(Bv * Hv, 16), 256>>>();

    gemm_bias<<<gg, 256>>>(y, Wp, bp, out, Mv, Cv, Cv);
}

// round 8
// speedup vs baseline: 2.0674x; 2.0674x over previous
#include <cuda_runtime.h>
#include <cuda_bf16.h>
#include <cstdint>

// Problem constants
#define Bv 4
#define Tv 4096
#define Cv 1024
#define Hv 16
#define Dh 64
#define Mv (Bv * Tv)          // 16384 rows
#define NSPLIT 16
#define NCHUNK 32

// ===================== scratch (device globals) ===========================
__device__ float g_q[Mv * Cv];
__device__ float g_k[Mv * Cv];
__device__ float g_v[Mv * Cv];
__device__ float g_y[Mv * Cv];
__device__ float g_ctx[Bv * Hv * Dh * Dh];
__device__ float g_ctx_part[NSPLIT * Bv * Hv * Dh * Dh];
__device__ float g_kcum[Bv * Cv];
__device__ float g_kcum_part[Bv * NCHUNK * Cv];

// bf16 split operand buffers
__device__ __nv_bfloat16 g_xs0[Mv * Cv];
__device__ __nv_bfloat16 g_xs1[Mv * Cv];
__device__ __nv_bfloat16 g_ys0[Mv * Cv];
__device__ __nv_bfloat16 g_ys1[Mv * Cv];
__device__ __nv_bfloat16 g_wqT0[Cv * Cv];    // transposed weight splits [N][K]
__device__ __nv_bfloat16 g_wqT1[Cv * Cv];
__device__ __nv_bfloat16 g_wkT0[Cv * Cv];
__device__ __nv_bfloat16 g_wkT1[Cv * Cv];
__device__ __nv_bfloat16 g_wvT0[Cv * Cv];
__device__ __nv_bfloat16 g_wvT1[Cv * Cv];
__device__ __nv_bfloat16 g_wpT0[Cv * Cv];
__device__ __nv_bfloat16 g_wpT1[Cv * Cv];

// ===================== PTX helpers (all base-target-safe) =================
__device__ __forceinline__ uint32_t smem_u32(const void* p) {
    uint32_t a;
    asm("{ .reg .u64 t; cvta.to.shared.u64 t, %1; cvt.u32.u64 %0, t; }"
        : "=r"(a) : "l"(p));
    return a;
}
__device__ __forceinline__ void cp16(uint32_t dst, const void* src) {
    asm volatile("cp.async.cg.shared.global [%0], [%1], 16;"
        :: "r"(dst), "l"(src));
}
__device__ __forceinline__ void cp_commit() {
    asm volatile("cp.async.commit_group;");
}
template<int N> __device__ __forceinline__ void cp_wait() {
    asm volatile("cp.async.wait_group %0;" :: "n"(N));
}
__device__ __forceinline__ void ldsm4(uint32_t* r, uint32_t addr) {
    asm volatile("ldmatrix.sync.aligned.m8n8.x4.shared.b16 {%0,%1,%2,%3}, [%4];"
        : "=r"(r[0]), "=r"(r[1]), "=r"(r[2]), "=r"(r[3]) : "r"(addr));
}
__device__ __forceinline__ void mma16816(float* d, const uint32_t* a, const uint32_t* b) {
    asm volatile(
        "mma.sync.aligned.m16n8k16.row.col.f32.bf16.bf16.f32 "
        "{%0,%1,%2,%3}, {%4,%5,%6,%7}, {%8,%9}, {%0,%1,%2,%3};"
        : "+f"(d[0]), "+f"(d[1]), "+f"(d[2]), "+f"(d[3])
        : "r"(a[0]), "r"(a[1]), "r"(a[2]), "r"(a[3]), "r"(b[0]), "r"(b[1]));
}

// ===================== bf16x2-split MMA GEMM ==============================
// C[16384][1024] = (A0+A1)[M][K] * (B0+B1)^T + bias,  B stored [N][K].
// Products fused in one K-pass: acc += A0B0 + A0B1 + A1B0 (A1B1 ~2^-18, dropped).
// CTA 128x128, BK=32, cp.async 3-stage pipeline, 8 warps (2M x 4N), warp
// tile 64x32, mma.sync m16n8k16 bf16.
#define GM_BM 128
#define GM_BN 128
#define GM_BK 32
#define GM_STAGES 3
#define GM_ROWB 80                        // 64B data + 16B pad (bank-cycle-free)
#define GM_TILE (128 * GM_ROWB)           // 10240 B
#define GM_STAGE (4 * GM_TILE)            // A0,A1,B0,B1 = 40960 B
#define GM_SMEM (GM_STAGES * GM_STAGE)    // 122880 B
#define GM_KCHUNKS (Cv / GM_BK)           // 32

__global__ void __launch_bounds__(256, 1)
gemm_mma(const __nv_bfloat16* __restrict__ A0, const __nv_bfloat16* __restrict__ A1,
         const __nv_bfloat16* __restrict__ B0, const __nv_bfloat16* __restrict__ B1,
         const float* __restrict__ bias, float* __restrict__ C)
{
    extern __shared__ char smem[];
    const uint32_t sb = smem_u32(smem);
    const int tid = threadIdx.x;
    const int n0 = blockIdx.x * GM_BN;
    const int m0 = blockIdx.y * GM_BM;

    const int l = tid & 31;
    const int wid = tid >> 5;
    const int warpM = wid & 1;        // 2 warps over M (64 rows each)
    const int warpN = wid >> 1;       // 4 warps over N (32 cols each)

    // ldmatrix per-lane geometry
    const int q = l >> 3;
    const int aRow  = warpM * 64 + (q & 1) * 8 + (l & 7);   // + mi*16
    const int aColB = (q >> 1) * 8;                         // + ks*16 (bf16 cols)
    const int bN    = warpN * 32 + (q >> 1) * 8 + (l & 7);  // + bj*16
    const int bColB = (q & 1) * 8;

    float acc[4][4][4];
#pragma unroll
    for (int i = 0; i < 4; i++)
#pragma unroll
        for (int j = 0; j < 4; j++)
#pragma unroll
            for (int r = 0; r < 4; r++) acc[i][j][r] = 0.f;

    // ---- async tile loader: chunk c -> stage st ----
    auto load_chunk = [&](int c, int st) {
        const int k0 = c * GM_BK;
        const uint32_t base = sb + st * GM_STAGE;
#pragma unroll
        for (int jj = 0; jj < 8; jj++) {
            int idx = tid + jj * 256;            // 0..2047
            int tile = idx >> 9;                 // 0:A0 1:A1 2:B0 3:B1
            int r    = (idx >> 2) & 127;
            int cc   = idx & 3;                  // 16B chunk
            const __nv_bfloat16* src;
            if (tile == 0)      src = A0 + (size_t)(m0 + r) * Cv + k0 + cc * 8;
            else if (tile == 1) src = A1 + (size_t)(m0 + r) * Cv + k0 + cc * 8;
            else if (tile == 2) src = B0 + (size_t)(n0 + r) * Cv + k0 + cc * 8;
            else                src = B1 + (size_t)(n0 + r) * Cv + k0 + cc * 8;
            cp16(base + tile * GM_TILE + r * GM_ROWB + cc * 16, src);
        }
    };

    // prologue: stages 0,1
    load_chunk(0, 0); cp_commit();
    load_chunk(1, 1); cp_commit();
    cp_wait<1>();
    __syncthreads();

    for (int i = 0; i < GM_KCHUNKS; i++) {
        const int st = i % GM_STAGES;
        if (i + 2 < GM_KCHUNKS) { load_chunk(i + 2, (i + 2) % GM_STAGES); cp_commit(); }

        const uint32_t stBase = sb + st * GM_STAGE;
#pragma unroll
        for (int ks = 0; ks < 2; ks++) {
            uint32_t a0f[4][4], a1f[4][4], b0f[2][4], b1f[2][4];
            const uint32_t aOff = (uint32_t)(ks * 16 + aColB) * 2;
            const uint32_t bOff = (uint32_t)(ks * 16 + bColB) * 2;
#pragma unroll
            for (int mi = 0; mi < 4; mi++) {
                uint32_t ra = stBase + (uint32_t)(aRow + mi * 16) * GM_ROWB + aOff;
                ldsm4(a0f[mi], ra);
                ldsm4(a1f[mi], ra + GM_TILE);
            }
#pragma unroll
            for (int bj = 0; bj < 2; bj++) {
                uint32_t rb = stBase + 2 * GM_TILE
                            + (uint32_t)(bN + bj * 16) * GM_ROWB + bOff;
                ldsm4(b0f[bj], rb);
                ldsm4(b1f[bj], rb + GM_TILE);
            }
#pragma unroll
            for (int mi = 0; mi < 4; mi++)
#pragma unroll
                for (int nj = 0; nj < 4; nj++) {
                    const uint32_t* bb0 = &b0f[nj >> 1][(nj & 1) * 2];
                    const uint32_t* bb1 = &b1f[nj >> 1][(nj & 1) * 2];
                    mma16816(acc[mi][nj], a0f[mi], bb0);   // A0*B0
                    mma16816(acc[mi][nj], a0f[mi], bb1);   // A0*B1
                    mma16816(acc[mi][nj], a1f[mi], bb0);   // A1*B0
                }
        }

        if (i + 2 < GM_KCHUNKS) cp_wait<1>(); else cp_wait<0>();
        __syncthreads();
    }

    // ---- epilogue: + bias, direct stores (float2 per reg pair) ----
    const int r0 = l >> 2;
    const int c0 = (l & 3) * 2;
#pragma unroll
    for (int nj = 0; nj < 4; nj++) {
        const int gcol = n0 + warpN * 32 + nj * 8 + c0;
        const float bx = bias[gcol], by = bias[gcol + 1];
#pragma unroll
        for (int mi = 0; mi < 4; mi++) {
            const int grow = m0 + warpM * 64 + mi * 16 + r0;
            float2 o0 = { acc[mi][nj][0] + bx, acc[mi][nj][1] + by };
            float2 o1 = { acc[mi][nj][2] + bx, acc[mi][nj][3] + by };
            *(float2*)&C[(size_t)grow * Cv + gcol] = o0;
            *(float2*)&C[(size_t)(grow + 8) * Cv + gcol] = o1;
        }
    }
}

// ===================== split kernels ======================================
__device__ __forceinline__ void split1(float a, __nv_bfloat16& hi, __nv_bfloat16& lo) {
    hi = __float2bfloat16_rn(a);
    lo = __float2bfloat16_rn(a - __bfloat162float(hi));
}

__global__ __launch_bounds__(256)
void split_act(const float* __restrict__ in,
               __nv_bfloat16* __restrict__ o0, __nv_bfloat16* __restrict__ o1)
{
    size_t i = (size_t)blockIdx.x * blockDim.x + threadIdx.x;   // one float4
    float4 v = ((const float4*)in)[i];
    __nv_bfloat16 h0, h1, h2, h3, l0, l1, l2, l3;
    split1(v.x, h0, l0); split1(v.y, h1, l1);
    split1(v.z, h2, l2); split1(v.w, h3, l3);
    ((__nv_bfloat162*)o0)[i * 2]     = __nv_bfloat162(h0, h1);
    ((__nv_bfloat162*)o0)[i * 2 + 1] = __nv_bfloat162(h2, h3);
    ((__nv_bfloat162*)o1)[i * 2]     = __nv_bfloat162(l0, l1);
    ((__nv_bfloat162*)o1)[i * 2 + 1] = __nv_bfloat162(l2, l3);
}

// weight transpose + split: W[K][N] fp32 -> T0,T1 [N][K] bf16
__global__ __launch_bounds__(256)
void split_wT(const float* __restrict__ W,
              __nv_bfloat16* __restrict__ T0, __nv_bfloat16* __restrict__ T1)
{
    __shared__ float t[32][33];
    int nb = blockIdx.x * 32, kb = blockIdx.y * 32;
    int tx = threadIdx.x & 31, ty = threadIdx.x >> 5;   // 32 x 8
    for (int r = ty; r < 32; r += 8)
        t[r][tx] = W[(size_t)(kb + r) * Cv + nb + tx];
    __syncthreads();
    for (int r = ty; r < 32; r += 8) {
        float a = t[tx][r];          // = W[kb+tx][nb+r]
        __nv_bfloat16 hi, lo;
        split1(a, hi, lo);
        T0[(size_t)(nb + r) * Cv + kb + tx] = hi;
        T1[(size_t)(nb + r) * Cv + kb + tx] = lo;
    }
}

// ===================== aux kernels (R2-proven) ============================
__global__ __launch_bounds__(256)
void softmax_head(float* __restrict__ X)
{
    int w    = (blockIdx.x * blockDim.x + threadIdx.x) >> 5;
    int lane = threadIdx.x & 31;
    int row  = w >> 4;
    int h    = w & 15;
    size_t base = (size_t)row * Cv + h * Dh;

    float a = X[base + lane];
    float b = X[base + lane + 32];
    float m = fmaxf(a, b);
#pragma unroll
    for (int o = 16; o > 0; o >>= 1) m = fmaxf(m, __shfl_xor_sync(~0u, m, o));
    a = __expf(a - m);
    b = __expf(b - m);
    float s = a + b;
#pragma unroll
    for (int o = 16; o > 0; o >>= 1) s += __shfl_xor_sync(~0u, s, o);
    float inv = 1.f / s;
    X[base + lane]      = a * inv;
    X[base + lane + 32] = b * inv;
}

__global__ __launch_bounds__(1024)
void kcum_part_kernel()
{
    int b = blockIdx.x;
    int chunk = blockIdx.y;
    int c = threadIdx.x;
    const float* kp = g_k + ((size_t)(b * Tv + chunk * (Tv / NCHUNK))) * Cv + c;
    float s = 0.f;
#pragma unroll 4
    for (int t = 0; t < Tv / NCHUNK; t++) s += kp[(size_t)t * Cv];
    g_kcum_part[((size_t)b * NCHUNK + chunk) * Cv + c] = s;
}

__global__ __launch_bounds__(256)
void kcum_reduce_kernel()
{
    int i = blockIdx.x * blockDim.x + threadIdx.x;
    int b = i >> 10, c = i & 1023;
    float s = 0.f;
#pragma unroll
    for (int ch = 0; ch < NCHUNK; ch++)
        s += g_kcum_part[((size_t)b * NCHUNK + ch) * Cv + c];
    g_kcum[i] = s;
}

__global__ __launch_bounds__(256)
void ctx_part_kernel()
{
    int bh = blockIdx.x;
    int b = bh >> 4, h = bh & 15;
    int split = blockIdx.y;
    const int TSPL = Tv / NSPLIT;

    __shared__ float ks[32][Dh];
    __shared__ float vs[32][Dh];

    int tid = threadIdx.x;
    int td = (tid >> 4) * 4;
    int te = (tid & 15) * 4;
    float acc[4][4];
#pragma unroll
    for (int i = 0; i < 4; i++)
#pragma unroll
        for (int j = 0; j < 4; j++) acc[i][j] = 0.f;

    int t0 = split * TSPL;
    for (int tc = 0; tc < TSPL; tc += 32) {
        for (int i = tid; i < 32 * 16; i += 256) {
            int r  = i >> 4;
            int c4 = (i & 15) * 4;
            size_t g = ((size_t)(b * Tv + t0 + tc + r)) * Cv + h * Dh + c4;
            *(float4*)&ks[r][c4] = *(const float4*)&g_k[g];
            *(float4*)&vs[r][c4] = *(const float4*)&g_v[g];
        }
        __syncthreads();
#pragma unroll 8
        for (int t = 0; t < 32; t++) {
            float kf[4], vf[4];
            *(float4*)kf = *(const float4*)&ks[t][td];
            *(float4*)vf = *(const float4*)&vs[t][te];
#pragma unroll
            for (int i = 0; i < 4; i++)
#pragma unroll
                for (int j = 0; j < 4; j++)
                    acc[i][j] += kf[i] * vf[j];
        }
        __syncthreads();
    }

    float* cp = &g_ctx_part[((size_t)split * (Bv * Hv) + bh) * Dh * Dh];
#pragma unroll
    for (int i = 0; i < 4; i++)
#pragma unroll
        for (int j = 0; j < 4; j++)
            cp[(td + i) * Dh + te + j] = acc[i][j];
}

__global__ __launch_bounds__(256)
void ctx_reduce_kernel()
{
    int i = blockIdx.x * blockDim.x + threadIdx.x;
    float s = 0.f;
#pragma unroll
    for (int sp = 0; sp < NSPLIT; sp++)
        s += g_ctx_part[(size_t)sp * (Bv * Hv * Dh * Dh) + i];
    g_ctx[i] = s;
}

__global__ __launch_bounds__(256)
void y_kernel()
{
    int bh = blockIdx.x;
    int b = bh >> 4, h = bh & 15;

    __shared__ float ctxs[Dh][Dh];
    __shared__ float kc[Dh];

    int tid = threadIdx.x;
    for (int i = tid; i < Dh * Dh / 4; i += 256)
        ((float4*)ctxs)[i] = ((const float4*)&g_ctx[(size_t)bh * Dh * Dh])[i];
    if (tid < Dh) kc[tid] = g_kcum[bh * Dh + tid];
    __syncthreads();

    int warp = tid >> 5, lane = tid & 31;
    int tbase = blockIdx.y * 256 + warp * 32;

    for (int ti = 0; ti < 32; ti++) {
        int t = tbase + ti;
        size_t base = ((size_t)(b * Tv + t)) * Cv + h * Dh;
        float qlo = g_q[base + lane];
        float qhi = g_q[base + lane + 32];

        float dp = qlo * kc[lane] + qhi * kc[lane + 32];
#pragma unroll
        for (int o = 16; o > 0; o >>= 1) dp += __shfl_xor_sync(~0u, dp, o);
        float dinv = 1.f / dp;

        float ylo = 0.f, yhi = 0.f;
#pragma unroll
        for (int d = 0; d < 32; d++) {
            float qd = __shfl_sync(~0u, qlo, d);
            ylo += qd * ctxs[d][lane];
            yhi += qd * ctxs[d][lane + 32];
        }
#pragma unroll
        for (int d = 0; d < 32; d++) {
            float qd = __shfl_sync(~0u, qhi, d);
            ylo += qd * ctxs[32 + d][lane];
            yhi += qd * ctxs[32 + d][lane + 32];
        }
        g_y[base + lane]      = ylo * dinv + qlo;
        g_y[base + lane + 32] = yhi * dinv + qhi;
    }
}

// ===================== launch =============================================
extern "C" void kernel_launch(void* const* d_in, const int* in_sizes, int n_in,
                              void* d_out, int out_size)
{
    const float* x  = (const float*)d_in[0];
    const float* Wq = (const float*)d_in[1];
    const float* bq = (const float*)d_in[2];
    const float* Wk = (const float*)d_in[3];
    const float* bk = (const float*)d_in[4];
    const float* Wv = (const float*)d_in[5];
    const float* bv = (const float*)d_in[6];
    const float* Wp = (const float*)d_in[7];
    const float* bp = (const float*)d_in[8];
    float* out = (float*)d_out;

    float *q, *k, *v, *y;
    cudaGetSymbolAddress((void**)&q, g_q);
    cudaGetSymbolAddress((void**)&k, g_k);
    cudaGetSymbolAddress((void**)&v, g_v);
    cudaGetSymbolAddress((void**)&y, g_y);
    __nv_bfloat16 *xs0, *xs1, *ys0, *ys1;
    __nv_bfloat16 *wqT0, *wqT1, *wkT0, *wkT1, *wvT0, *wvT1, *wpT0, *wpT1;
    cudaGetSymbolAddress((void**)&xs0, g_xs0);
    cudaGetSymbolAddress((void**)&xs1, g_xs1);
    cudaGetSymbolAddress((void**)&ys0, g_ys0);
    cudaGetSymbolAddress((void**)&ys1, g_ys1);
    cudaGetSymbolAddress((void**)&wqT0, g_wqT0);
    cudaGetSymbolAddress((void**)&wqT1, g_wqT1);
    cudaGetSymbolAddress((void**)&wkT0, g_wkT0);
    cudaGetSymbolAddress((void**)&wkT1, g_wkT1);
    cudaGetSymbolAddress((void**)&wvT0, g_wvT0);
    cudaGetSymbolAddress((void**)&wvT1, g_wvT1);
    cudaGetSymbolAddress((void**)&wpT0, g_wpT0);
    cudaGetSymbolAddress((void**)&wpT1, g_wpT1);

    cudaFuncSetAttribute(gemm_mma, cudaFuncAttributeMaxDynamicSharedMemorySize,
                         GM_SMEM);

    // operand preparation
    split_act<<<(Mv * Cv / 4) / 256, 256>>>(x, xs0, xs1);
    dim3 wt(32, 32);
    split_wT<<<wt, 256>>>(Wq, wqT0, wqT1);
    split_wT<<<wt, 256>>>(Wk, wkT0, wkT1);
    split_wT<<<wt, 256>>>(Wv, wvT0, wvT1);
    split_wT<<<wt, 256>>>(Wp, wpT0, wpT1);

    dim3 gg(Cv / GM_BN, Mv / GM_BM);   // (8, 128)
    gemm_mma<<<gg, 256, GM_SMEM>>>(xs0, xs1, wqT0, wqT1, bq, q);
    gemm_mma<<<gg, 256, GM_SMEM>>>(xs0, xs1, wkT0, wkT1, bk, k);
    gemm_mma<<<gg, 256, GM_SMEM>>>(xs0, xs1, wvT0, wvT1, bv, v);

    softmax_head<<<(Mv * Hv) / 8, 256>>>(q);
    softmax_head<<<(Mv * Hv) / 8, 256>>>(k);

    kcum_part_kernel<<<dim3(Bv, NCHUNK), 1024>>>();
    kcum_reduce_kernel<<<(Bv * Cv) / 256, 256>>>();
    ctx_part_kernel<<<dim3(Bv * Hv, NSPLIT), 256>>>();
    ctx_reduce_kernel<<<(Bv * Hv * Dh * Dh) / 256, 256>>>();
    y_kernel<<<dim3(Bv * Hv, 16), 256>>>();

    split_act<<<(Mv * Cv / 4) / 256, 256>>>(y, ys0, ys1);
    gemm_mma<<<gg, 256, GM_SMEM>>>(ys0, ys1, wpT0, wpT1, bp, out);
}